// round 11
// baseline (speedup 1.0000x reference)
#include <cuda_runtime.h>
#include <math_constants.h>
#include <cstdint>

// Problem constants
#define NROWS 1048576
#define HDIM  128
#define NSEG  128
#define NEG_SLOPE 0.01f
#define LOG2E 1.4426950408889634f

// TMA tiling
#define TILE_ROWS 64
#define TILE_BYTES (TILE_ROWS * HDIM * 4)          // 32768
#define STAGES 3
#define TILES_PER_BLOCK 8
#define ROWS_PER_BLOCK (TILE_ROWS * TILES_PER_BLOCK)   // 512
#define THREADS_PER_BLOCK 256
#define WARPS_PER_BLOCK 8
#define NUM_BLOCKS (NROWS / ROWS_PER_BLOCK)        // 2048

// Dynamic smem layout: [0,48): mbarriers (full[s]=s*16, empty[s]=s*16+8)
//                      [1024, 1024+3*32768): tile ring
#define SMEM_TILE0 1024
#define SMEM_DYN (SMEM_TILE0 + STAGES * TILE_BYTES)    // 99328

// Scratch (device globals)
__device__ float g_qs[NSEG];
__device__ float g_d[NSEG];
__device__ float g_acc[NSEG * HDIM];
__device__ int   g_done;

// ---------------------------------------------------------------------------
// PTX helpers (self-contained)
// ---------------------------------------------------------------------------
__device__ __forceinline__ unsigned smem_u32(const void* p) {
    unsigned a;
    asm("{ .reg .u64 t; cvta.to.shared.u64 t, %1; cvt.u32.u64 %0, t; }"
        : "=r"(a) : "l"(p));
    return a;
}
#define MBARRIER_INIT(addr, cnt) \
    asm volatile("mbarrier.init.shared.b64 [%0], %1;" \
                 :: "r"((unsigned)(addr)), "r"((unsigned)(cnt)) : "memory")
#define MBARRIER_EXPECT_TX(addr, bytes) \
    asm volatile("mbarrier.arrive.expect_tx.shared.b64 _, [%0], %1;" \
                 :: "r"((unsigned)(addr)), "r"((unsigned)(bytes)) : "memory")
#define MBARRIER_ARRIVE(addr) \
    asm volatile("mbarrier.arrive.release.cta.shared.b64 _, [%0];" \
                 :: "r"((unsigned)(addr)) : "memory")
#define MBARRIER_WAIT_PARITY(addr, parity) do {                               \
    unsigned _m = (unsigned)(addr); unsigned _p = (unsigned)(parity);         \
    asm volatile(                                                             \
        "{\n\t.reg .pred P;\n\t"                                              \
        "WAIT_%=:\n\t"                                                        \
        "mbarrier.try_wait.parity.acquire.cta.shared::cta.b64 P, [%0], %1, 0x989680;\n\t" \
        "@P bra.uni DONE_%=;\n\t"                                             \
        "bra.uni WAIT_%=;\n\t"                                                \
        "DONE_%=:\n\t}"                                                       \
        :: "r"(_m), "r"(_p) : "memory");                                      \
} while (0)

__device__ __forceinline__ void bulk_cp(unsigned dst_smem, const void* src,
                                        unsigned bytes, unsigned mbar) {
    asm volatile(
        "cp.async.bulk.shared::cluster.global.mbarrier::complete_tx::bytes "
        "[%0], [%1], %2, [%3];"
        :: "r"(dst_smem), "l"(src), "r"(bytes), "r"(mbar) : "memory");
}

// ---------------------------------------------------------------------------
// Kernel 1: q_score[b] = (aq[b] . w[H:2H]) * LOG2E; zero accumulators.
// ---------------------------------------------------------------------------
__global__ void __launch_bounds__(HDIM)
prep_kernel(const float* __restrict__ aq, const float* __restrict__ w)
{
    const int b = blockIdx.x;
    const int t = threadIdx.x;
    const int lane = t & 31;
    g_acc[b * HDIM + t] = 0.f;
    if (t == 0) g_d[b] = 0.f;

    float v = aq[(size_t)b * HDIM + t] * w[HDIM + t];
#pragma unroll
    for (int off = 16; off; off >>= 1)
        v += __shfl_xor_sync(0xffffffffu, v, off);
    __shared__ float sm[4];
    if (lane == 0) sm[t >> 5] = v;
    __syncthreads();
    if (t == 0) g_qs[b] = ((sm[0] + sm[1]) + (sm[2] + sm[3])) * LOG2E;
}

// ---------------------------------------------------------------------------
// process8 (R3-proven, verbatim). Lane l owns columns [4l, 4l+4).
// ---------------------------------------------------------------------------
__device__ __forceinline__ void process8(const float4 hv[8],
                                         float4& acc, float& d,
                                         float qsc, float4 w4, int lane)
{
    float p[8];
#pragma unroll
    for (int j = 0; j < 8; j++)
        p[j] = fmaf(hv[j].x, w4.x,
               fmaf(hv[j].y, w4.y,
               fmaf(hv[j].z, w4.z, hv[j].w * w4.w)));

    const bool h16 = (lane & 16) != 0;
    const bool h8  = (lane & 8)  != 0;
    const bool h4b = (lane & 4)  != 0;

    float a[4];
#pragma unroll
    for (int j = 0; j < 4; j++) {
        float send = h16 ? p[j]     : p[j + 4];
        float keep = h16 ? p[j + 4] : p[j];
        a[j] = keep + __shfl_xor_sync(0xffffffffu, send, 16);
    }
    float bb[2];
#pragma unroll
    for (int j = 0; j < 2; j++) {
        float send = h8 ? a[j]     : a[j + 2];
        float keep = h8 ? a[j + 2] : a[j];
        bb[j] = keep + __shfl_xor_sync(0xffffffffu, send, 8);
    }
    {
        float send = h4b ? bb[0] : bb[1];
        float keep = h4b ? bb[1] : bb[0];
        float c = keep + __shfl_xor_sync(0xffffffffu, send, 4);
        c += __shfl_xor_sync(0xffffffffu, c, 2);
        c += __shfl_xor_sync(0xffffffffu, c, 1);
        p[0] = c;
    }

    float e[8];
#pragma unroll
    for (int j = 0; j < 8; j++) {
        float g = __shfl_sync(0xffffffffu, p[0], j * 4) + qsc;
        g = fmaxf(g, NEG_SLOPE * g);
        e[j] = exp2f(g);
    }

    d += ((e[0] + e[1]) + (e[2] + e[3])) + ((e[4] + e[5]) + (e[6] + e[7]));

#define WSUM_COMP(comp)                                            \
    do {                                                           \
        float s0 = fmaf(e[1], hv[1].comp, e[0] * hv[0].comp);      \
        float s1 = fmaf(e[3], hv[3].comp, e[2] * hv[2].comp);      \
        float s2 = fmaf(e[5], hv[5].comp, e[4] * hv[4].comp);      \
        float s3 = fmaf(e[7], hv[7].comp, e[6] * hv[6].comp);      \
        acc.comp += (s0 + s1) + (s2 + s3);                         \
    } while (0)
    WSUM_COMP(x); WSUM_COMP(y); WSUM_COMP(z); WSUM_COMP(w);
#undef WSUM_COMP
}

__device__ __forceinline__ void flush_atomic(int segid, float d, float4 acc,
                                             int lane)
{
    if (lane == 0) atomicAdd(&g_d[segid], d);
    float* dst = g_acc + (size_t)segid * HDIM + lane * 4;
    atomicAdd(dst + 0, acc.x);
    atomicAdd(dst + 1, acc.y);
    atomicAdd(dst + 2, acc.z);
    atomicAdd(dst + 3, acc.w);
}

// ---------------------------------------------------------------------------
// Kernel 2: TMA-bulk-fed gate + segment softmax-sum + last-block finalize.
// Block streams 512 contiguous rows as 8 tiles of 64 rows through a 3-stage
// smem ring filled by cp.async.bulk (bypasses L1TEX entirely).
// ---------------------------------------------------------------------------
__global__ void __launch_bounds__(THREADS_PER_BLOCK)
gate_pool_kernel(const float* __restrict__ h,
                 const float* __restrict__ w,
                 const int*   __restrict__ seg,
                 float* __restrict__ out)
{
    extern __shared__ char smem[];
    const unsigned sbase = smem_u32(smem);
    const int tid  = threadIdx.x;
    const int lane = tid & 31;
    const int wib  = tid >> 5;
    const int row0 = blockIdx.x * ROWS_PER_BLOCK;

    if (tid == 0) {
#pragma unroll
        for (int s = 0; s < STAGES; s++) {
            MBARRIER_INIT(sbase + s * 16,     1);                 // full
            MBARRIER_INIT(sbase + s * 16 + 8, WARPS_PER_BLOCK);   // empty
        }
    }
    __syncthreads();

    // Prologue: fill all 3 stages.
    if (tid == 0) {
#pragma unroll
        for (int s = 0; s < STAGES; s++) {
            const unsigned fb = sbase + s * 16;
            MBARRIER_EXPECT_TX(fb, TILE_BYTES);
            const char* src = (const char*)h
                            + (size_t)(row0 + s * TILE_ROWS) * (HDIM * 4);
            bulk_cp(sbase + SMEM_TILE0 + s * TILE_BYTES, src,
                    TILE_BYTES / 2, fb);
            bulk_cp(sbase + SMEM_TILE0 + s * TILE_BYTES + TILE_BYTES / 2,
                    src + TILE_BYTES / 2, TILE_BYTES / 2, fb);
        }
    }

    float4 w4 = reinterpret_cast<const float4*>(w)[lane];
    w4.x *= LOG2E; w4.y *= LOG2E; w4.z *= LOG2E; w4.w *= LOG2E;

    float4 acc = make_float4(0.f, 0.f, 0.f, 0.f);
    float d = 0.f;
    int cur = -1;
    float qsc = 0.f;

#pragma unroll 1
    for (int t = 0; t < TILES_PER_BLOCK; t++) {
        const int s = t % STAGES;
        const unsigned fb = sbase + s * 16;
        const unsigned eb = fb + 8;
        const int ph = (t / STAGES) & 1;

        MBARRIER_WAIT_PARITY(fb, ph);

        const float4* stile =
            (const float4*)(smem + SMEM_TILE0 + s * TILE_BYTES);
        const int rbase = row0 + t * TILE_ROWS + wib * 8;

        int s8 = seg[rbase + (lane & 7)];
        int sf = __shfl_sync(0xffffffffu, s8, 0);
        int sl = __shfl_sync(0xffffffffu, s8, 7);

        float4 hv[8];
#pragma unroll
        for (int j = 0; j < 8; j++)
            hv[j] = stile[(wib * 8 + j) * 32 + lane];

        if (sf == sl) {
            // fast path: warp's 8 rows in one segment
            if (sf != cur) {
                if (cur >= 0) flush_atomic(cur, d, acc, lane);
                d = 0.f;
                acc = make_float4(0.f, 0.f, 0.f, 0.f);
                cur = sf;
                qsc = g_qs[sf];
            }
            process8(hv, acc, d, qsc, w4, lane);
        } else {
            // slow path: boundary among these 8 rows
#pragma unroll
            for (int j = 0; j < 8; j++) {
                float p = fmaf(hv[j].x, w4.x,
                          fmaf(hv[j].y, w4.y,
                          fmaf(hv[j].z, w4.z, hv[j].w * w4.w)));
#pragma unroll
                for (int off = 16; off; off >>= 1)
                    p += __shfl_xor_sync(0xffffffffu, p, off);

                int sr = __shfl_sync(0xffffffffu, s8, j);
                if (sr != cur) {
                    if (cur >= 0) flush_atomic(cur, d, acc, lane);
                    d = 0.f;
                    acc = make_float4(0.f, 0.f, 0.f, 0.f);
                    cur = sr;
                    qsc = g_qs[sr];
                }
                float gate = p + qsc;
                gate = fmaxf(gate, NEG_SLOPE * gate);
                float e = exp2f(gate);
                d += e;
                acc.x = fmaf(e, hv[j].x, acc.x);
                acc.y = fmaf(e, hv[j].y, acc.y);
                acc.z = fmaf(e, hv[j].z, acc.z);
                acc.w = fmaf(e, hv[j].w, acc.w);
            }
        }

        __syncwarp();
        if (lane == 0) MBARRIER_ARRIVE(eb);

        // Refill this stage with tile t+3 (producer = thread 0).
        if (t + STAGES < TILES_PER_BLOCK && tid == 0) {
            MBARRIER_WAIT_PARITY(eb, ph);
            MBARRIER_EXPECT_TX(fb, TILE_BYTES);
            const char* src = (const char*)h
                + (size_t)(row0 + (t + STAGES) * TILE_ROWS) * (HDIM * 4);
            bulk_cp(sbase + SMEM_TILE0 + s * TILE_BYTES, src,
                    TILE_BYTES / 2, fb);
            bulk_cp(sbase + SMEM_TILE0 + s * TILE_BYTES + TILE_BYTES / 2,
                    src + TILE_BYTES / 2, TILE_BYTES / 2, fb);
        }
    }

    if (cur >= 0) flush_atomic(cur, d, acc, lane);

    // ---------------- cold tail: last block finalizes ------------------------
    __shared__ int sticket;
    __syncthreads();
    if (tid == 0) {
        __threadfence();
        sticket = atomicAdd(&g_done, 1);
    }
    __syncthreads();

    if (sticket == (int)gridDim.x - 1) {
        __threadfence();
        __shared__ float sinv[NSEG];
        if (tid < NSEG) {
            float dv = __ldcg(&g_d[tid]);
            sinv[tid] = 1.f / fmaxf(dv, 1e-20f);
        }
        __syncthreads();
#pragma unroll 4
        for (int i = tid; i < NSEG * HDIM; i += THREADS_PER_BLOCK)
            out[i] = __ldcg(&g_acc[i]) * sinv[i >> 7];
        if (tid == 0) g_done = 0;
    }
}

// ---------------------------------------------------------------------------
// Launch: inputs per metadata order: h, attention_query, w, segment_ids.
// ---------------------------------------------------------------------------
extern "C" void kernel_launch(void* const* d_in, const int* in_sizes, int n_in,
                              void* d_out, int out_size)
{
    const float* h   = (const float*)d_in[0];
    const float* aq  = (const float*)d_in[1];
    const float* w   = (const float*)d_in[2];
    const int*   seg = (const int*)d_in[3];
    float* out = (float*)d_out;

    // Opt-in to >48KB dynamic smem (idempotent, no allocation).
    cudaFuncSetAttribute(gate_pool_kernel,
                         cudaFuncAttributeMaxDynamicSharedMemorySize, SMEM_DYN);

    prep_kernel<<<NSEG, HDIM>>>(aq, w);
    gate_pool_kernel<<<NUM_BLOCKS, THREADS_PER_BLOCK, SMEM_DYN>>>(
        h, w, seg, out);
}

// round 12
// speedup vs baseline: 1.4835x; 1.4835x over previous
#include <cuda_runtime.h>
#include <math_constants.h>

// Problem constants
#define NROWS 1048576
#define HDIM  128
#define NSEG  128
#define NEG_SLOPE 0.01f
#define LOG2E 1.4426950408889634f

// Tiling
#define ROWS_PER_WARP 256
#define ROWS_PER_ITER 8
#define NUM_ITERS (ROWS_PER_WARP / ROWS_PER_ITER)     // 32
#define WARPS_PER_BLOCK 4
#define THREADS_PER_BLOCK (WARPS_PER_BLOCK * 32)      // 128
#define NUM_WARPS (NROWS / ROWS_PER_WARP)             // 4096
#define NUM_BLOCKS (NUM_WARPS / WARPS_PER_BLOCK)      // 1024

// Scratch (device globals — zero-initialized; kernel restores zeros at end)
__device__ float g_qs[NSEG];                 // q_score * LOG2E
__device__ float g_d[NSEG];                  // sum of exp
__device__ float g_acc[NSEG * HDIM];         // sum of exp * h

// ---------------------------------------------------------------------------
// Kernel 1: q_score[b] = (attention_query[b] . w[H:2H]) * LOG2E; zero accums.
// ---------------------------------------------------------------------------
__global__ void __launch_bounds__(HDIM)
prep_kernel(const float* __restrict__ aq, const float* __restrict__ w)
{
    const int b = blockIdx.x;
    const int t = threadIdx.x;
    const int lane = t & 31;
    g_acc[b * HDIM + t] = 0.f;
    if (t == 0) g_d[b] = 0.f;

    float v = aq[(size_t)b * HDIM + t] * w[HDIM + t];
#pragma unroll
    for (int off = 16; off; off >>= 1)
        v += __shfl_xor_sync(0xffffffffu, v, off);
    __shared__ float sm[4];
    if (lane == 0) sm[t >> 5] = v;
    __syncthreads();
    if (t == 0) g_qs[b] = ((sm[0] + sm[1]) + (sm[2] + sm[3])) * LOG2E;
}

// ---------------------------------------------------------------------------
// Process one batch of 8 rows (fast path). Lane l owns columns [4l, 4l+4).
// ---------------------------------------------------------------------------
__device__ __forceinline__ void process8(const float4 hv[ROWS_PER_ITER],
                                         float4& acc, float& d,
                                         float qsc, float4 w4, int lane)
{
    float p[8];
#pragma unroll
    for (int j = 0; j < 8; j++)
        p[j] = fmaf(hv[j].x, w4.x,
               fmaf(hv[j].y, w4.y,
               fmaf(hv[j].z, w4.z, hv[j].w * w4.w)));

    // Lane-group tree reduce (17 SHFL total instead of 40)
    const bool h16 = (lane & 16) != 0;
    const bool h8  = (lane & 8)  != 0;
    const bool h4b = (lane & 4)  != 0;

    float a[4];
#pragma unroll
    for (int j = 0; j < 4; j++) {
        float send = h16 ? p[j]     : p[j + 4];
        float keep = h16 ? p[j + 4] : p[j];
        a[j] = keep + __shfl_xor_sync(0xffffffffu, send, 16);
    }
    float bb[2];
#pragma unroll
    for (int j = 0; j < 2; j++) {
        float send = h8 ? a[j]     : a[j + 2];
        float keep = h8 ? a[j + 2] : a[j];
        bb[j] = keep + __shfl_xor_sync(0xffffffffu, send, 8);
    }
    {
        float send = h4b ? bb[0] : bb[1];
        float keep = h4b ? bb[1] : bb[0];
        float c = keep + __shfl_xor_sync(0xffffffffu, send, 4);
        c += __shfl_xor_sync(0xffffffffu, c, 2);
        c += __shfl_xor_sync(0xffffffffu, c, 1);
        p[0] = c;   // reuse: lane 4j now holds full sum for row j
    }

    // Broadcast row sums, gate (pre-scaled by LOG2E), leaky relu, exp2.
    float e[8];
#pragma unroll
    for (int j = 0; j < 8; j++) {
        float g = __shfl_sync(0xffffffffu, p[0], j * 4) + qsc;
        g = fmaxf(g, NEG_SLOPE * g);
        e[j] = exp2f(g);
    }

    d += ((e[0] + e[1]) + (e[2] + e[3])) + ((e[4] + e[5]) + (e[6] + e[7]));

#define WSUM_COMP(comp)                                            \
    do {                                                           \
        float s0 = fmaf(e[1], hv[1].comp, e[0] * hv[0].comp);      \
        float s1 = fmaf(e[3], hv[3].comp, e[2] * hv[2].comp);      \
        float s2 = fmaf(e[5], hv[5].comp, e[4] * hv[4].comp);      \
        float s3 = fmaf(e[7], hv[7].comp, e[6] * hv[6].comp);      \
        acc.comp += (s0 + s1) + (s2 + s3);                         \
    } while (0)
    WSUM_COMP(x); WSUM_COMP(y); WSUM_COMP(z); WSUM_COMP(w);
#undef WSUM_COMP
}

// Atomic flush of a partial (d, acc) into segment accumulators.
__device__ __forceinline__ void flush_atomic(int segid, float d, float4 acc,
                                             int lane)
{
    if (lane == 0) atomicAdd(&g_d[segid], d);
    float* dst = g_acc + (size_t)segid * HDIM + lane * 4;
    atomicAdd(dst + 0, acc.x);
    atomicAdd(dst + 1, acc.y);
    atomicAdd(dst + 2, acc.z);
    atomicAdd(dst + 3, acc.w);
}

// ---------------------------------------------------------------------------
// Kernel 2: single-pass segment softmax-sum (no max subtraction needed:
// gates are O(1) by construction; softmax is shift-invariant).
// One warp streams 256 contiguous rows with double-buffered 8-row batches.
// ---------------------------------------------------------------------------
__global__ void __launch_bounds__(THREADS_PER_BLOCK)
gate_pool_kernel(const float4* __restrict__ h4,
                 const float*  __restrict__ w,
                 const int*    __restrict__ seg)
{
    const int lane = threadIdx.x & 31;
    const int warp_gid = blockIdx.x * WARPS_PER_BLOCK + (threadIdx.x >> 5);
    const int row0 = warp_gid * ROWS_PER_WARP;
    const size_t stride = HDIM / 4;   // float4 per row

    float4 w4 = reinterpret_cast<const float4*>(w)[lane];
    w4.x *= LOG2E; w4.y *= LOG2E; w4.z *= LOG2E; w4.w *= LOG2E;

    float4 acc = make_float4(0.f, 0.f, 0.f, 0.f);
    float d = 0.f;
    int cur = seg[row0];
    const int last = seg[row0 + ROWS_PER_WARP - 1];
    const float4* base = h4 + (size_t)row0 * stride + lane;

    if (cur == last) {
        // ---------------- FAST PATH: single segment in chunk ----------------
        const float qsc = g_qs[cur];
        float4 A[ROWS_PER_ITER], B[ROWS_PER_ITER];

#pragma unroll
        for (int j = 0; j < ROWS_PER_ITER; j++)
            A[j] = __ldcs(base + (size_t)j * stride);

        for (int it = 0; it < NUM_ITERS; it += 2) {
            const float4* pB = base + (size_t)(it + 1) * ROWS_PER_ITER * stride;
#pragma unroll
            for (int j = 0; j < ROWS_PER_ITER; j++)
                B[j] = __ldcs(pB + (size_t)j * stride);

            process8(A, acc, d, qsc, w4, lane);

            if (it + 2 < NUM_ITERS) {
                const float4* pA = base + (size_t)(it + 2) * ROWS_PER_ITER * stride;
#pragma unroll
                for (int j = 0; j < ROWS_PER_ITER; j++)
                    A[j] = __ldcs(pA + (size_t)j * stride);
            }

            process8(B, acc, d, qsc, w4, lane);
        }
        flush_atomic(cur, d, acc, lane);
    } else {
        // ---------------- SLOW PATH: boundary inside chunk ------------------
        float qsc = g_qs[cur];
        for (int r = row0; r < row0 + ROWS_PER_WARP; r += ROWS_PER_ITER) {
            float4 hv[ROWS_PER_ITER];
#pragma unroll
            for (int j = 0; j < ROWS_PER_ITER; j++)
                hv[j] = __ldcs(base + (size_t)(r - row0 + j) * stride);

            int s8 = seg[r + (lane & 7)];

            float g[ROWS_PER_ITER];
#pragma unroll
            for (int j = 0; j < ROWS_PER_ITER; j++) {
                float p = fmaf(hv[j].x, w4.x,
                          fmaf(hv[j].y, w4.y,
                          fmaf(hv[j].z, w4.z, hv[j].w * w4.w)));
#pragma unroll
                for (int off = 16; off; off >>= 1)
                    p += __shfl_xor_sync(0xffffffffu, p, off);
                g[j] = p;
            }

#pragma unroll
            for (int j = 0; j < ROWS_PER_ITER; j++) {
                int s = __shfl_sync(0xffffffffu, s8, j);
                if (s != cur) {
                    flush_atomic(cur, d, acc, lane);
                    d = 0.f;
                    acc = make_float4(0.f, 0.f, 0.f, 0.f);
                    cur = s;
                    qsc = g_qs[s];
                }
                float gate = g[j] + qsc;
                gate = fmaxf(gate, NEG_SLOPE * gate);
                float e = exp2f(gate);
                d += e;
                acc.x = fmaf(e, hv[j].x, acc.x);
                acc.y = fmaf(e, hv[j].y, acc.y);
                acc.z = fmaf(e, hv[j].z, acc.z);
                acc.w = fmaf(e, hv[j].w, acc.w);
            }
        }
        flush_atomic(cur, d, acc, lane);
    }
}

// ---------------------------------------------------------------------------
// Kernel 3: out[b][t] = acc[b][t] / max(d[b], 1e-20).
// ---------------------------------------------------------------------------
__global__ void __launch_bounds__(HDIM)
finalize_kernel(float* __restrict__ out)
{
    const int b = blockIdx.x;
    const int t = threadIdx.x;
    out[(size_t)b * HDIM + t] =
        g_acc[(size_t)b * HDIM + t] / fmaxf(g_d[b], 1e-20f);
}

// ---------------------------------------------------------------------------
// Launch: inputs per metadata order: h, attention_query, w, segment_ids.
// ---------------------------------------------------------------------------
extern "C" void kernel_launch(void* const* d_in, const int* in_sizes, int n_in,
                              void* d_out, int out_size)
{
    const float* h   = (const float*)d_in[0];
    const float* aq  = (const float*)d_in[1];
    const float* w   = (const float*)d_in[2];
    const int*   seg = (const int*)d_in[3];
    float* out = (float*)d_out;

    prep_kernel<<<NSEG, HDIM>>>(aq, w);
    gate_pool_kernel<<<NUM_BLOCKS, THREADS_PER_BLOCK>>>(
        (const float4*)h, w, seg);
    finalize_kernel<<<NSEG, HDIM>>>(out);
}